// round 15
// baseline (speedup 1.0000x reference)
#include <cuda_runtime.h>
#include <cuda_bf16.h>
#include <cstdint>

#define B_ 2
#define T_ 2048
#define D_ 1024
#define NH_ 16
#define KH_ 8
#define H_ 128

static constexpr float SCALE_ = 0.08838834764831845f;   // 128^-0.5
static constexpr float KMASK_ = -3.4028234663852886e38f;

// Scratch (device globals; no runtime allocation allowed)
__device__ float g_q[(size_t)B_ * NH_ * T_ * H_];   // [B][N][T][H] (tf32-rounded)
__device__ float g_k[(size_t)B_ * KH_ * T_ * H_];   // [B][K][S][H] (tf32-rounded)
__device__ float g_v[(size_t)B_ * KH_ * T_ * H_];   // [B][K][S][H] (tf32-rounded)
__device__ float g_o[(size_t)B_ * T_ * NH_ * H_];   // [B][T][N][H] (tf32-rounded)
__device__ int   g_pos[B_ * T_];
// tf32-rounded copies of inputs
__device__ float g_x [(size_t)B_ * T_ * D_];
__device__ float g_wq[(size_t)D_ * NH_ * H_];
__device__ float g_wk[(size_t)D_ * KH_ * H_];
__device__ float g_wv[(size_t)D_ * KH_ * H_];
__device__ float g_wo[(size_t)NH_ * H_ * D_];

// ---------------------------------------------------------------------------
__device__ __forceinline__ uint32_t f2tf32(float x) {
    uint32_t r;
    asm("cvt.rna.tf32.f32 %0, %1;" : "=r"(r) : "f"(x));
    return r;
}

__device__ __forceinline__ void mma_tf32(float* c,
                                         uint32_t a0, uint32_t a1, uint32_t a2, uint32_t a3,
                                         uint32_t b0, uint32_t b1) {
    asm volatile(
        "mma.sync.aligned.m16n8k8.row.col.f32.tf32.tf32.f32 "
        "{%0,%1,%2,%3}, {%4,%5,%6,%7}, {%8,%9}, {%0,%1,%2,%3};\n"
        : "+f"(c[0]), "+f"(c[1]), "+f"(c[2]), "+f"(c[3])
        : "r"(a0), "r"(a1), "r"(a2), "r"(a3), "r"(b0), "r"(b1));
}

__device__ __forceinline__ void cpa16(uint32_t saddr, const void* gptr) {
    asm volatile("cp.async.ca.shared.global [%0], [%1], 16;\n"
                 :: "r"(saddr), "l"(gptr));
}
__device__ __forceinline__ void cpa_commit() {
    asm volatile("cp.async.commit_group;\n" ::: "memory");
}
__device__ __forceinline__ void cpa_wait0() {
    asm volatile("cp.async.wait_group 0;\n" ::: "memory");
}
__device__ __forceinline__ void cpa_wait1() {
    asm volatile("cp.async.wait_group 1;\n" ::: "memory");
}

// ---------------------------------------------------------------------------
// Positions from segment ids.
// ---------------------------------------------------------------------------
__global__ __launch_bounds__(256) void pos_kernel(const int* __restrict__ seg) {
    int b = blockIdx.x;
    int tid = threadIdx.x;
    __shared__ int sred[256];

    int mv = -2147483647 - 1;
    for (int t = tid; t < T_; t += 256) mv = max(mv, seg[b * T_ + t]);
    sred[tid] = mv;
    __syncthreads();
    for (int st = 128; st > 0; st >>= 1) {
        if (tid < st) sred[tid] = max(sred[tid], sred[tid + st]);
        __syncthreads();
    }
    int maxv = sred[0];
    __syncthreads();

    int mi = 0x7fffffff;
    for (int t = tid; t < T_; t += 256)
        if (seg[b * T_ + t] == maxv) mi = min(mi, t);
    sred[tid] = mi;
    __syncthreads();
    for (int st = 128; st > 0; st >>= 1) {
        if (tid < st) sred[tid] = min(sred[tid], sred[tid + st]);
        __syncthreads();
    }
    int off = sred[0];

    for (int t = tid; t < T_; t += 256) {
        int s = seg[b * T_ + t];
        g_pos[b * T_ + t] = (s != 0) ? (t - off) : (1 << 30);
    }
}

// ---------------------------------------------------------------------------
// Round x to tf32 into g_x.
// ---------------------------------------------------------------------------
__global__ __launch_bounds__(256) void round_x_kernel(const float* __restrict__ src) {
    const int n4 = (B_ * T_ * D_) / 4;
    int i = blockIdx.x * 256 + threadIdx.x;
    int stride = gridDim.x * 256;
    for (; i < n4; i += stride) {
        float4 v = *(const float4*)(src + (size_t)i * 4);
        v.x = __uint_as_float(f2tf32(v.x));
        v.y = __uint_as_float(f2tf32(v.y));
        v.z = __uint_as_float(f2tf32(v.z));
        v.w = __uint_as_float(f2tf32(v.w));
        *(float4*)(g_x + (size_t)i * 4) = v;
    }
}

// ---------------------------------------------------------------------------
// Round all 4 weight tensors to tf32 (flat index over concat).
// ---------------------------------------------------------------------------
__global__ __launch_bounds__(256) void round_w_kernel(const float* __restrict__ wq,
                                                      const float* __restrict__ wk,
                                                      const float* __restrict__ wv,
                                                      const float* __restrict__ wo) {
    const int N4 = 1572864;
    int i = blockIdx.x * 256 + threadIdx.x;
    int stride = gridDim.x * 256;
    for (; i < N4; i += stride) {
        const float* src;
        float* dst;
        int j;
        if (i < 524288)       { src = wq; dst = g_wq; j = i; }
        else if (i < 786432)  { src = wk; dst = g_wk; j = i - 524288; }
        else if (i < 1048576) { src = wv; dst = g_wv; j = i - 786432; }
        else                  { src = wo; dst = g_wo; j = i - 1048576; }
        float4 v = *(const float4*)(src + (size_t)j * 4);
        v.x = __uint_as_float(f2tf32(v.x));
        v.y = __uint_as_float(f2tf32(v.y));
        v.z = __uint_as_float(f2tf32(v.z));
        v.w = __uint_as_float(f2tf32(v.w));
        *(float4*)(dst + (size_t)j * 4) = v;
    }
}

// ---------------------------------------------------------------------------
// QKV projection GEMM: 128 threads / 4 warps, warp tile 64x64 (mt4 x nt8).
// 1.0 smem word per MMA. cp.async 2-stage, dyn smem 71,680B.
// ---------------------------------------------------------------------------
#define GEMM_SA_WORDS (2 * 128 * 36)
#define GEMM_SB_WORDS (2 * 32 * 136)
#define GEMM_SMEM_BYTES ((GEMM_SA_WORDS + GEMM_SB_WORDS) * 4)

__global__ __launch_bounds__(128) void sgemm_qkv() {
    extern __shared__ uint32_t smg[];
    uint32_t* sA = smg;
    uint32_t* sB = smg + GEMM_SA_WORDS;

    int tid = threadIdx.x;
    int warp = tid >> 5, lane = tid & 31;
    int g = lane >> 2, qd = lane & 3;
    int wm = warp & 1, wn = warp >> 1;   // wm 0..1 (64 rows), wn 0..1 (64 cols)

    int cn = blockIdx.x * 128;
    int rm = blockIdx.y * 128;

    const float* W;
    int ldb, mode, colOff;
    if (cn < 2048)      { W = g_wq; ldb = NH_ * H_; colOff = cn;        mode = 0; }
    else if (cn < 3072) { W = g_wk; ldb = KH_ * H_; colOff = cn - 2048; mode = 1; }
    else                { W = g_wv; ldb = KH_ * H_; colOff = cn - 3072; mode = 2; }
    int head = colOff >> 7;

    uint32_t sA_base = (uint32_t)__cvta_generic_to_shared(sA);
    uint32_t sB_base = (uint32_t)__cvta_generic_to_shared(sB);

    int arA = tid >> 3, acA = (tid & 7) << 2;      // A: 16 rows/pass x 8 passes
    int arB = tid >> 5, acB = (tid & 31) << 2;     // B: 4 rows/pass x 8 passes

    float c[4][8][4];
#pragma unroll
    for (int mt = 0; mt < 4; mt++)
#pragma unroll
        for (int nt = 0; nt < 8; nt++)
#pragma unroll
            for (int i = 0; i < 4; i++) c[mt][nt][i] = 0.0f;

    auto load_stage = [&](int kk, int st) {
#pragma unroll
        for (int i = 0; i < 8; i++) {
            int r = arA + i * 16;
            cpa16(sA_base + (st * 128 * 36 + r * 36 + acA) * 4,
                  g_x + (size_t)(rm + r) * D_ + kk + acA);
        }
#pragma unroll
        for (int i = 0; i < 8; i++) {
            int r = arB + i * 4;
            cpa16(sB_base + (st * 32 * 136 + r * 136 + acB) * 4,
                  W + (size_t)(kk + r) * ldb + colOff + acB);
        }
        cpa_commit();
    };

    load_stage(0, 0);

    const int KT = D_ / 32;
    for (int kt = 0; kt < KT; kt++) {
        if (kt + 1 < KT) load_stage((kt + 1) * 32, (kt + 1) & 1);
        if (kt + 1 < KT) cpa_wait1(); else cpa_wait0();
        __syncthreads();

        const uint32_t* A  = sA + (kt & 1) * 128 * 36;
        const uint32_t* Bm = sB + (kt & 1) * 32 * 136;
#pragma unroll
        for (int ks = 0; ks < 4; ks++) {
            int k0 = ks * 8;
            uint32_t a[4][4];
#pragma unroll
            for (int mt = 0; mt < 4; mt++) {
                int ar = wm * 64 + mt * 16 + g;
                a[mt][0] = A[ar * 36 + k0 + qd];
                a[mt][1] = A[(ar + 8) * 36 + k0 + qd];
                a[mt][2] = A[ar * 36 + k0 + 4 + qd];
                a[mt][3] = A[(ar + 8) * 36 + k0 + 4 + qd];
            }
            uint32_t b[8][2];
#pragma unroll
            for (int nt = 0; nt < 8; nt++) {
                int bc = wn * 64 + nt * 8 + g;
                b[nt][0] = Bm[(k0 + qd) * 136 + bc];
                b[nt][1] = Bm[(k0 + 4 + qd) * 136 + bc];
            }
#pragma unroll
            for (int mt = 0; mt < 4; mt++)
#pragma unroll
                for (int nt = 0; nt < 8; nt++)
                    mma_tf32(c[mt][nt], a[mt][0], a[mt][1], a[mt][2], a[mt][3],
                             b[nt][0], b[nt][1]);
        }
        __syncthreads();
    }

    float* base = (mode == 0) ? g_q : (mode == 1 ? g_k : g_v);
    int heads = (mode == 0) ? NH_ : KH_;
    bool roundV = (mode == 2);
#pragma unroll
    for (int mt = 0; mt < 4; mt++) {
#pragma unroll
        for (int nt = 0; nt < 8; nt++) {
            int col = wn * 64 + nt * 8 + qd * 2;
            int rr0 = rm + wm * 64 + mt * 16 + g;
            int rr1 = rr0 + 8;
            int b0 = rr0 >> 11, t0 = rr0 & 2047;
            int b1 = rr1 >> 11, t1 = rr1 & 2047;
            float* d0 = base + ((size_t)(b0 * heads + head) * T_ + t0) * H_ + col;
            float* d1 = base + ((size_t)(b1 * heads + head) * T_ + t1) * H_ + col;
            float v0 = c[mt][nt][0], v1 = c[mt][nt][1];
            float v2 = c[mt][nt][2], v3 = c[mt][nt][3];
            if (roundV) {
                v0 = __uint_as_float(f2tf32(v0));
                v1 = __uint_as_float(f2tf32(v1));
                v2 = __uint_as_float(f2tf32(v2));
                v3 = __uint_as_float(f2tf32(v3));
            }
            *(float2*)d0 = make_float2(v0, v1);
            *(float2*)d1 = make_float2(v2, v3);
        }
    }
}

// ---------------------------------------------------------------------------
// RMSNorm + RoPE, warp-per-row (8 rows per 256-thr block), no block barriers.
// ---------------------------------------------------------------------------
__global__ __launch_bounds__(256) void norm_rope_kernel(const float* __restrict__ qscale,
                                                        const float* __restrict__ kscale) {
    int wid = threadIdx.x >> 5, lane = threadIdx.x & 31;
    int row = blockIdx.x * 8 + wid;
    const int QROWS = B_ * NH_ * T_;
    float* data;
    const float* scale;
    int b, t;
    if (row < QROWS) {
        data = g_q + (size_t)row * H_;
        scale = qscale;
        b = row / (NH_ * T_);
        t = row % T_;
    } else {
        int r = row - QROWS;
        data = g_k + (size_t)r * H_;
        scale = kscale;
        b = r / (KH_ * T_);
        t = r % T_;
    }

    float4 v = *(const float4*)(data + lane * 4);
    float ss = v.x * v.x + v.y * v.y + v.z * v.z + v.w * v.w;
#pragma unroll
    for (int o = 16; o; o >>= 1) ss += __shfl_xor_sync(0xffffffffu, ss, o);
    float rinv = rsqrtf(ss * (1.0f / 128.0f) + 1e-6f);

    float4 sc = *(const float4*)(scale + lane * 4);
    float x[4] = { sc.x * v.x * rinv, sc.y * v.y * rinv,
                   sc.z * v.z * rinv, sc.w * v.w * rinv };

    int pos = g_pos[b * T_ + t];
    int j = lane & 15;
    bool lowHalf = (lane < 16);
    float out[4];
#pragma unroll
    for (int k = 0; k < 4; k++) {
        int idx = j * 4 + k;
        float inv = exp2f(-((float)idx * (1.0f / 64.0f)) * 19.931568569324174f);
        float ang = (float)pos * inv;
        float sn, cs;
        sincosf(ang, &sn, &cs);
        float xo = __shfl_xor_sync(0xffffffffu, x[k], 16);
        float r = lowHalf ? (x[k] * cs - xo * sn) : (x[k] * cs + xo * sn);
        out[k] = __uint_as_float(f2tf32(r));
    }
    *(float4*)(data + lane * 4) = make_float4(out[0], out[1], out[2], out[3]);
}

// ---------------------------------------------------------------------------
// Flash attention (EXACT R14): FA2-style warp ownership, 8 warps x 16 rows,
// register softmax, 2 barriers/tile. Q tile 128, KV 64, LPT. smem 174,080B.
// ---------------------------------------------------------------------------
#define SQ_OFF   0
#define SK_OFF   (SQ_OFF + 128 * 132)
#define SV_OFF   (SK_OFF + 64 * 132)
#define SS_OFF   (SV_OFF + 64 * 136)
#define PT_OFF   (SS_OFF + 128 * 68)
#define ST_OFF   (PT_OFF + 128)
#define PS_OFF   (ST_OFF + 128)
#define SSG_OFF  (PS_OFF + 64)
#define ATTN_SMEM_WORDS (SSG_OFF + 64)

__global__ __launch_bounds__(256, 1) void attn_kernel(const int* __restrict__ seg) {
    extern __shared__ uint32_t smu[];
    uint32_t* sQ  = smu + SQ_OFF;
    uint32_t* sK  = smu + SK_OFF;
    uint32_t* sV  = smu + SV_OFF;
    uint32_t* sSu = smu + SS_OFF;
    int*      sPT = (int*)(smu + PT_OFF);
    int*      sST = (int*)(smu + ST_OFF);
    int*      sPS = (int*)(smu + PS_OFF);
    int*      sSG = (int*)(smu + SSG_OFF);

    uint32_t smem_base = (uint32_t)__cvta_generic_to_shared(smu);

    int tid = threadIdx.x;
    int warp = tid >> 5, lane = tid & 31;
    int g = lane >> 2, qd = lane & 3;

    int bid = blockIdx.x;
    int itile = 15 - (bid & 15);
    int n  = (bid >> 4) & 15;
    int b  = bid >> 8;
    int kvh = n >> 1;
    int t0 = itile * 128;

    const float* Qb = g_q + (size_t)(b * NH_ + n)   * T_ * H_;
    const float* Kb = g_k + (size_t)(b * KH_ + kvh) * T_ * H_;
    const float* Vb = g_v + (size_t)(b * KH_ + kvh) * T_ * H_;
    const int* posb = g_pos + b * T_;
    const int* segb = seg + b * T_;

    int lr = tid >> 5;
    int lc = (tid & 31) << 2;

#pragma unroll
    for (int i = 0; i < 16; i++) {
        int r = lr + i * 8;
        cpa16(smem_base + (SQ_OFF + r * 132 + lc) * 4,
              Qb + (size_t)(t0 + r) * H_ + lc);
    }
    cpa_commit();

    if (tid < 128) {
        sPT[tid] = posb[t0 + tid];
        sST[tid] = segb[t0 + tid];
    }

    int r0 = warp * 16 + g, r1 = r0 + 8;

    float m0 = -3.0e38f, m1 = -3.0e38f, l0 = 0.0f, l1 = 0.0f;

    float cO[16][4];
#pragma unroll
    for (int i = 0; i < 16; i++)
#pragma unroll
        for (int j = 0; j < 4; j++) cO[i][j] = 0.0f;

    int numjt = 2 * itile + 2;
    for (int jt = 0; jt < numjt; jt++) {
        int s0 = jt * 64;

#pragma unroll
        for (int i = 0; i < 8; i++) {
            int r = lr + i * 8;
            cpa16(smem_base + (SK_OFF + r * 132 + lc) * 4,
                  Kb + (size_t)(s0 + r) * H_ + lc);
            cpa16(smem_base + (SV_OFF + r * 136 + lc) * 4,
                  Vb + (size_t)(s0 + r) * H_ + lc);
        }
        cpa_commit();
        if (tid < 64) {
            sPS[tid] = posb[s0 + tid];
            sSG[tid] = segb[s0 + tid];
        }
        cpa_wait0();
        __syncthreads();

        float cS[8][4];
#pragma unroll
        for (int nt = 0; nt < 8; nt++)
#pragma unroll
            for (int j = 0; j < 4; j++) cS[nt][j] = 0.0f;

#pragma unroll
        for (int k0 = 0; k0 < 128; k0 += 8) {
            uint32_t a0 = sQ[r0 * 132 + k0 + qd];
            uint32_t a1 = sQ[r1 * 132 + k0 + qd];
            uint32_t a2 = sQ[r0 * 132 + k0 + 4 + qd];
            uint32_t a3 = sQ[r1 * 132 + k0 + 4 + qd];
#pragma unroll
            for (int nt = 0; nt < 8; nt++) {
                int bc = nt * 8 + g;
                uint32_t b0 = sK[bc * 132 + k0 + qd];
                uint32_t b1 = sK[bc * 132 + k0 + 4 + qd];
                mma_tf32(cS[nt], a0, a1, a2, a3, b0, b1);
            }
        }

        int pt0 = sPT[r0], st0 = sST[r0];
        int pt1 = sPT[r1], st1 = sST[r1];
        float v0[8][2], v1[8][2];
#pragma unroll
        for (int nt = 0; nt < 8; nt++) {
            int col = nt * 8 + qd * 2;
            int ps0 = sPS[col], ss0 = sSG[col];
            int ps1 = sPS[col + 1], ss1 = sSG[col + 1];
            v0[nt][0] = (ps0 <= pt0 && ss0 == st0) ? cS[nt][0] * SCALE_ : KMASK_;
            v0[nt][1] = (ps1 <= pt0 && ss1 == st0) ? cS[nt][1] * SCALE_ : KMASK_;
            v1[nt][0] = (ps0 <= pt1 && ss0 == st1) ? cS[nt][2] * SCALE_ : KMASK_;
            v1[nt][1] = (ps1 <= pt1 && ss1 == st1) ? cS[nt][3] * SCALE_ : KMASK_;
        }

        float mx0 = KMASK_, mx1 = KMASK_;
#pragma unroll
        for (int nt = 0; nt < 8; nt++) {
            mx0 = fmaxf(mx0, fmaxf(v0[nt][0], v0[nt][1]));
            mx1 = fmaxf(mx1, fmaxf(v1[nt][0], v1[nt][1]));
        }
        mx0 = fmaxf(mx0, __shfl_xor_sync(0xffffffffu, mx0, 1));
        mx0 = fmaxf(mx0, __shfl_xor_sync(0xffffffffu, mx0, 2));
        mx1 = fmaxf(mx1, __shfl_xor_sync(0xffffffffu, mx1, 1));
        mx1 = fmaxf(mx1, __shfl_xor_sync(0xffffffffu, mx1, 2));
        float mn0 = fmaxf(m0, mx0), mn1 = fmaxf(m1, mx1);

        float sum0 = 0.0f, sum1 = 0.0f;
#pragma unroll
        for (int nt = 0; nt < 8; nt++) {
            int col = nt * 8 + qd * 2;
            float p00 = __expf(v0[nt][0] - mn0);
            float p01 = __expf(v0[nt][1] - mn0);
            float p10 = __expf(v1[nt][0] - mn1);
            float p11 = __expf(v1[nt][1] - mn1);
            sum0 += p00 + p01;
            sum1 += p10 + p11;
            sSu[r0 * 68 + col]     = f2tf32(p00);
            sSu[r0 * 68 + col + 1] = f2tf32(p01);
            sSu[r1 * 68 + col]     = f2tf32(p10);
            sSu[r1 * 68 + col + 1] = f2tf32(p11);
        }
        sum0 += __shfl_xor_sync(0xffffffffu, sum0, 1);
        sum0 += __shfl_xor_sync(0xffffffffu, sum0, 2);
        sum1 += __shfl_xor_sync(0xffffffffu, sum1, 1);
        sum1 += __shfl_xor_sync(0xffffffffu, sum1, 2);

        float f0 = __expf(m0 - mn0), f1 = __expf(m1 - mn1);
        l0 = l0 * f0 + sum0;
        l1 = l1 * f1 + sum1;
        m0 = mn0; m1 = mn1;

#pragma unroll
        for (int nt = 0; nt < 16; nt++) {
            cO[nt][0] *= f0; cO[nt][1] *= f0;
            cO[nt][2] *= f1; cO[nt][3] *= f1;
        }
        __syncwarp();

#pragma unroll
        for (int k0 = 0; k0 < 64; k0 += 8) {
            uint32_t a0 = sSu[r0 * 68 + k0 + qd];
            uint32_t a1 = sSu[r1 * 68 + k0 + qd];
            uint32_t a2 = sSu[r0 * 68 + k0 + 4 + qd];
            uint32_t a3 = sSu[r1 * 68 + k0 + 4 + qd];
#pragma unroll
            for (int nt = 0; nt < 16; nt++) {
                int vc = nt * 8 + g;
                uint32_t b0 = sV[(k0 + qd) * 136 + vc];
                uint32_t b1 = sV[(k0 + 4 + qd) * 136 + vc];
                mma_tf32(cO[nt], a0, a1, a2, a3, b0, b1);
            }
        }
        __syncthreads();
    }

    float inv0 = 1.0f / l0;
    float inv1 = 1.0f / l1;
#pragma unroll
    for (int nt = 0; nt < 16; nt++) {
        int col = nt * 8 + qd * 2;
        float* d0 = g_o + ((size_t)(b * T_ + t0 + r0) * NH_ + n) * H_ + col;
        float* d1 = g_o + ((size_t)(b * T_ + t0 + r1) * NH_ + n) * H_ + col;
        *(float2*)d0 = make_float2(__uint_as_float(f2tf32(cO[nt][0] * inv0)),
                                   __uint_as_float(f2tf32(cO[nt][1] * inv0)));
        *(float2*)d1 = make_float2(__uint_as_float(f2tf32(cO[nt][2] * inv1)),
                                   __uint_as_float(f2tf32(cO[nt][3] * inv1)));
    }
}

// ---------------------------------------------------------------------------
// Output projection: 128 threads / 4 warps, warp tile 64x64 (mt4 x nt8).
// ---------------------------------------------------------------------------
__global__ __launch_bounds__(128) void sgemm_out(float* __restrict__ out) {
    extern __shared__ uint32_t smg[];
    uint32_t* sA = smg;
    uint32_t* sB = smg + GEMM_SA_WORDS;

    int tid = threadIdx.x;
    int warp = tid >> 5, lane = tid & 31;
    int g = lane >> 2, qd = lane & 3;
    int wm = warp & 1, wn = warp >> 1;

    int cn = blockIdx.x * 128;
    int rm = blockIdx.y * 128;

    uint32_t sA_base = (uint32_t)__cvta_generic_to_shared(sA);
    uint32_t sB_base = (uint32_t)__cvta_generic_to_shared(sB);

    int arA = tid >> 3, acA = (tid & 7) << 2;
    int arB = tid >> 5, acB = (tid & 31) << 2;

    float c[4][8][4];
#pragma unroll
    for (int mt = 0; mt < 4; mt++)
#pragma unroll
        for (int nt = 0; nt < 8; nt++)
#pragma unroll
            for (int i = 0; i < 4; i++) c[mt][nt][i] = 0.0f;

    auto load_stage = [&](int kk, int st) {
#pragma unroll
        for (int i = 0; i < 8; i++) {
            int r = arA + i * 16;
            cpa16(sA_base + (st * 128 * 36 + r * 36 + acA) * 4,
                  g_o + (size_t)(rm + r) * (NH_ * H_) + kk + acA);
        }
#pragma unroll
        for (int i = 0; i < 8; i++) {
            int r = arB + i * 4;
            cpa16(sB_base + (st * 32 * 136 + r * 136 + acB) * 4,
                  g_wo + (size_t)(kk + r) * D_ + cn + acB);
        }
        cpa_commit();
    };

    load_stage(0, 0);

    const int KT = (NH_ * H_) / 32;
    for (int kt = 0; kt < KT; kt++) {
        if (kt + 1 < KT) load_stage((kt + 1) * 32, (kt + 1) & 1);
        if (kt + 1 < KT) cpa_wait1(); else cpa_wait0();
        __syncthreads();

        const uint32_t* A  = sA + (kt & 1) * 128 * 36;
        const uint32_t* Bm = sB + (kt & 1) * 32 * 136;
#pragma unroll
        for (int ks = 0; ks < 4; ks++) {
            int k0 = ks * 8;
            uint32_t a[4][4];
#pragma unroll
            for (int mt = 0; mt < 4; mt++) {
                int ar = wm * 64 + mt * 16 + g;
                a[mt][0] = A[ar * 36 + k0 + qd];
                a[mt][1] = A[(ar + 8) * 36 + k0 + qd];
                a[mt][2] = A[ar * 36 + k0 + 4 + qd];
                a[mt][3] = A[(ar + 8) * 36 + k0 + 4 + qd];
            }
            uint32_t b[8][2];
#pragma unroll
            for (int nt = 0; nt < 8; nt++) {
                int bc = wn * 64 + nt * 8 + g;
                b[nt][0] = Bm[(k0 + qd) * 136 + bc];
                b[nt][1] = Bm[(k0 + 4 + qd) * 136 + bc];
            }
#pragma unroll
            for (int mt = 0; mt < 4; mt++)
#pragma unroll
                for (int nt = 0; nt < 8; nt++)
                    mma_tf32(c[mt][nt], a[mt][0], a[mt][1], a[mt][2], a[mt][3],
                             b[nt][0], b[nt][1]);
        }
        __syncthreads();
    }

#pragma unroll
    for (int mt = 0; mt < 4; mt++) {
#pragma unroll
        for (int nt = 0; nt < 8; nt++) {
            int col = cn + wn * 64 + nt * 8 + qd * 2;
            int rr0 = rm + wm * 64 + mt * 16 + g;
            int rr1 = rr0 + 8;
            *(float2*)(out + (size_t)rr0 * D_ + col) = make_float2(c[mt][nt][0], c[mt][nt][1]);
            *(float2*)(out + (size_t)rr1 * D_ + col) = make_float2(c[mt][nt][2], c[mt][nt][3]);
        }
    }
}

// ---------------------------------------------------------------------------
extern "C" void kernel_launch(void* const* d_in, const int* in_sizes, int n_in,
                              void* d_out, int out_size) {
    const float* x  = (const float*)d_in[0];
    const int*   sg = (const int*)d_in[1];
    const float* wq = (const float*)d_in[2];
    const float* wk = (const float*)d_in[3];
    const float* wv = (const float*)d_in[4];
    const float* wo = (const float*)d_in[5];
    const float* qs = (const float*)d_in[6];
    const float* ks = (const float*)d_in[7];
    float* out = (float*)d_out;

    cudaFuncSetAttribute(sgemm_qkv, cudaFuncAttributeMaxDynamicSharedMemorySize,
                         GEMM_SMEM_BYTES);
    cudaFuncSetAttribute(sgemm_out, cudaFuncAttributeMaxDynamicSharedMemorySize,
                         GEMM_SMEM_BYTES);
    cudaFuncSetAttribute(attn_kernel, cudaFuncAttributeMaxDynamicSharedMemorySize,
                         ATTN_SMEM_WORDS * 4);

    pos_kernel<<<B_, 256>>>(sg);                                        // 1
    round_x_kernel<<<512, 256>>>(x);                                    // 2
    round_w_kernel<<<512, 256>>>(wq, wk, wv, wo);                       // 3
    sgemm_qkv<<<dim3(32, 32), 128, GEMM_SMEM_BYTES>>>();                // 4
    norm_rope_kernel<<<(B_ * (NH_ + KH_) * T_) / 8, 256>>>(qs, ks);     // 5
    attn_kernel<<<B_ * NH_ * 16, 256, ATTN_SMEM_WORDS * 4>>>(sg);       // 6
    sgemm_out<<<dim3(8, 32), 128, GEMM_SMEM_BYTES>>>(out);              // 7
}

// round 16
// speedup vs baseline: 1.0439x; 1.0439x over previous
#include <cuda_runtime.h>
#include <cuda_bf16.h>
#include <cstdint>

#define B_ 2
#define T_ 2048
#define D_ 1024
#define NH_ 16
#define KH_ 8
#define H_ 128

static constexpr float SCALE_ = 0.08838834764831845f;   // 128^-0.5
static constexpr float KMASK_ = -3.4028234663852886e38f;

// Scratch (device globals; no runtime allocation allowed)
__device__ float g_q[(size_t)B_ * NH_ * T_ * H_];   // [B][N][T][H] (tf32-rounded)
__device__ float g_k[(size_t)B_ * KH_ * T_ * H_];   // [B][K][S][H] (tf32-rounded)
__device__ float g_v[(size_t)B_ * KH_ * T_ * H_];   // [B][K][S][H] (tf32-rounded)
__device__ float g_o[(size_t)B_ * T_ * NH_ * H_];   // [B][T][N][H] (tf32-rounded)
__device__ int   g_pos[B_ * T_];
// tf32-rounded copies of inputs
__device__ float g_x [(size_t)B_ * T_ * D_];
__device__ float g_wq[(size_t)D_ * NH_ * H_];
__device__ float g_wk[(size_t)D_ * KH_ * H_];
__device__ float g_wv[(size_t)D_ * KH_ * H_];
__device__ float g_wo[(size_t)NH_ * H_ * D_];

// ---------------------------------------------------------------------------
__device__ __forceinline__ uint32_t f2tf32(float x) {
    uint32_t r;
    asm("cvt.rna.tf32.f32 %0, %1;" : "=r"(r) : "f"(x));
    return r;
}

__device__ __forceinline__ void mma_tf32(float* c,
                                         uint32_t a0, uint32_t a1, uint32_t a2, uint32_t a3,
                                         uint32_t b0, uint32_t b1) {
    asm volatile(
        "mma.sync.aligned.m16n8k8.row.col.f32.tf32.tf32.f32 "
        "{%0,%1,%2,%3}, {%4,%5,%6,%7}, {%8,%9}, {%0,%1,%2,%3};\n"
        : "+f"(c[0]), "+f"(c[1]), "+f"(c[2]), "+f"(c[3])
        : "r"(a0), "r"(a1), "r"(a2), "r"(a3), "r"(b0), "r"(b1));
}

__device__ __forceinline__ void cpa16(uint32_t saddr, const void* gptr) {
    asm volatile("cp.async.ca.shared.global [%0], [%1], 16;\n"
                 :: "r"(saddr), "l"(gptr));
}
__device__ __forceinline__ void cpa_commit() {
    asm volatile("cp.async.commit_group;\n" ::: "memory");
}
__device__ __forceinline__ void cpa_wait0() {
    asm volatile("cp.async.wait_group 0;\n" ::: "memory");
}
__device__ __forceinline__ void cpa_wait1() {
    asm volatile("cp.async.wait_group 1;\n" ::: "memory");
}

// ---------------------------------------------------------------------------
// Positions from segment ids.
// ---------------------------------------------------------------------------
__global__ __launch_bounds__(256) void pos_kernel(const int* __restrict__ seg) {
    int b = blockIdx.x;
    int tid = threadIdx.x;
    __shared__ int sred[256];

    int mv = -2147483647 - 1;
    for (int t = tid; t < T_; t += 256) mv = max(mv, seg[b * T_ + t]);
    sred[tid] = mv;
    __syncthreads();
    for (int st = 128; st > 0; st >>= 1) {
        if (tid < st) sred[tid] = max(sred[tid], sred[tid + st]);
        __syncthreads();
    }
    int maxv = sred[0];
    __syncthreads();

    int mi = 0x7fffffff;
    for (int t = tid; t < T_; t += 256)
        if (seg[b * T_ + t] == maxv) mi = min(mi, t);
    sred[tid] = mi;
    __syncthreads();
    for (int st = 128; st > 0; st >>= 1) {
        if (tid < st) sred[tid] = min(sred[tid], sred[tid + st]);
        __syncthreads();
    }
    int off = sred[0];

    for (int t = tid; t < T_; t += 256) {
        int s = seg[b * T_ + t];
        g_pos[b * T_ + t] = (s != 0) ? (t - off) : (1 << 30);
    }
}

// ---------------------------------------------------------------------------
// Round x to tf32 into g_x.
// ---------------------------------------------------------------------------
__global__ __launch_bounds__(256) void round_x_kernel(const float* __restrict__ src) {
    const int n4 = (B_ * T_ * D_) / 4;
    int i = blockIdx.x * 256 + threadIdx.x;
    int stride = gridDim.x * 256;
    for (; i < n4; i += stride) {
        float4 v = *(const float4*)(src + (size_t)i * 4);
        v.x = __uint_as_float(f2tf32(v.x));
        v.y = __uint_as_float(f2tf32(v.y));
        v.z = __uint_as_float(f2tf32(v.z));
        v.w = __uint_as_float(f2tf32(v.w));
        *(float4*)(g_x + (size_t)i * 4) = v;
    }
}

// ---------------------------------------------------------------------------
// Round all 4 weight tensors to tf32 (flat index over concat).
// ---------------------------------------------------------------------------
__global__ __launch_bounds__(256) void round_w_kernel(const float* __restrict__ wq,
                                                      const float* __restrict__ wk,
                                                      const float* __restrict__ wv,
                                                      const float* __restrict__ wo) {
    const int N4 = 1572864;
    int i = blockIdx.x * 256 + threadIdx.x;
    int stride = gridDim.x * 256;
    for (; i < N4; i += stride) {
        const float* src;
        float* dst;
        int j;
        if (i < 524288)       { src = wq; dst = g_wq; j = i; }
        else if (i < 786432)  { src = wk; dst = g_wk; j = i - 524288; }
        else if (i < 1048576) { src = wv; dst = g_wv; j = i - 786432; }
        else                  { src = wo; dst = g_wo; j = i - 1048576; }
        float4 v = *(const float4*)(src + (size_t)j * 4);
        v.x = __uint_as_float(f2tf32(v.x));
        v.y = __uint_as_float(f2tf32(v.y));
        v.z = __uint_as_float(f2tf32(v.z));
        v.w = __uint_as_float(f2tf32(v.w));
        *(float4*)(dst + (size_t)j * 4) = v;
    }
}

// ---------------------------------------------------------------------------
// QKV projection GEMM: 128 threads / 4 warps, warp tile 64x64 (R15, measured
// best). cp.async 2-stage, dyn smem 71,680B.
// ---------------------------------------------------------------------------
#define GEMM_SA_WORDS (2 * 128 * 36)
#define GEMM_SB_WORDS (2 * 32 * 136)
#define GEMM_SMEM_BYTES ((GEMM_SA_WORDS + GEMM_SB_WORDS) * 4)

__global__ __launch_bounds__(128) void sgemm_qkv() {
    extern __shared__ uint32_t smg[];
    uint32_t* sA = smg;
    uint32_t* sB = smg + GEMM_SA_WORDS;

    int tid = threadIdx.x;
    int warp = tid >> 5, lane = tid & 31;
    int g = lane >> 2, qd = lane & 3;
    int wm = warp & 1, wn = warp >> 1;

    int cn = blockIdx.x * 128;
    int rm = blockIdx.y * 128;

    const float* W;
    int ldb, mode, colOff;
    if (cn < 2048)      { W = g_wq; ldb = NH_ * H_; colOff = cn;        mode = 0; }
    else if (cn < 3072) { W = g_wk; ldb = KH_ * H_; colOff = cn - 2048; mode = 1; }
    else                { W = g_wv; ldb = KH_ * H_; colOff = cn - 3072; mode = 2; }
    int head = colOff >> 7;

    uint32_t sA_base = (uint32_t)__cvta_generic_to_shared(sA);
    uint32_t sB_base = (uint32_t)__cvta_generic_to_shared(sB);

    int arA = tid >> 3, acA = (tid & 7) << 2;
    int arB = tid >> 5, acB = (tid & 31) << 2;

    float c[4][8][4];
#pragma unroll
    for (int mt = 0; mt < 4; mt++)
#pragma unroll
        for (int nt = 0; nt < 8; nt++)
#pragma unroll
            for (int i = 0; i < 4; i++) c[mt][nt][i] = 0.0f;

    auto load_stage = [&](int kk, int st) {
#pragma unroll
        for (int i = 0; i < 8; i++) {
            int r = arA + i * 16;
            cpa16(sA_base + (st * 128 * 36 + r * 36 + acA) * 4,
                  g_x + (size_t)(rm + r) * D_ + kk + acA);
        }
#pragma unroll
        for (int i = 0; i < 8; i++) {
            int r = arB + i * 4;
            cpa16(sB_base + (st * 32 * 136 + r * 136 + acB) * 4,
                  W + (size_t)(kk + r) * ldb + colOff + acB);
        }
        cpa_commit();
    };

    load_stage(0, 0);

    const int KT = D_ / 32;
    for (int kt = 0; kt < KT; kt++) {
        if (kt + 1 < KT) load_stage((kt + 1) * 32, (kt + 1) & 1);
        if (kt + 1 < KT) cpa_wait1(); else cpa_wait0();
        __syncthreads();

        const uint32_t* A  = sA + (kt & 1) * 128 * 36;
        const uint32_t* Bm = sB + (kt & 1) * 32 * 136;
#pragma unroll
        for (int ks = 0; ks < 4; ks++) {
            int k0 = ks * 8;
            uint32_t a[4][4];
#pragma unroll
            for (int mt = 0; mt < 4; mt++) {
                int ar = wm * 64 + mt * 16 + g;
                a[mt][0] = A[ar * 36 + k0 + qd];
                a[mt][1] = A[(ar + 8) * 36 + k0 + qd];
                a[mt][2] = A[ar * 36 + k0 + 4 + qd];
                a[mt][3] = A[(ar + 8) * 36 + k0 + 4 + qd];
            }
            uint32_t b[8][2];
#pragma unroll
            for (int nt = 0; nt < 8; nt++) {
                int bc = wn * 64 + nt * 8 + g;
                b[nt][0] = Bm[(k0 + qd) * 136 + bc];
                b[nt][1] = Bm[(k0 + 4 + qd) * 136 + bc];
            }
#pragma unroll
            for (int mt = 0; mt < 4; mt++)
#pragma unroll
                for (int nt = 0; nt < 8; nt++)
                    mma_tf32(c[mt][nt], a[mt][0], a[mt][1], a[mt][2], a[mt][3],
                             b[nt][0], b[nt][1]);
        }
        __syncthreads();
    }

    float* base = (mode == 0) ? g_q : (mode == 1 ? g_k : g_v);
    int heads = (mode == 0) ? NH_ : KH_;
    bool roundV = (mode == 2);
#pragma unroll
    for (int mt = 0; mt < 4; mt++) {
#pragma unroll
        for (int nt = 0; nt < 8; nt++) {
            int col = wn * 64 + nt * 8 + qd * 2;
            int rr0 = rm + wm * 64 + mt * 16 + g;
            int rr1 = rr0 + 8;
            int b0 = rr0 >> 11, t0 = rr0 & 2047;
            int b1 = rr1 >> 11, t1 = rr1 & 2047;
            float* d0 = base + ((size_t)(b0 * heads + head) * T_ + t0) * H_ + col;
            float* d1 = base + ((size_t)(b1 * heads + head) * T_ + t1) * H_ + col;
            float v0 = c[mt][nt][0], v1 = c[mt][nt][1];
            float v2 = c[mt][nt][2], v3 = c[mt][nt][3];
            if (roundV) {
                v0 = __uint_as_float(f2tf32(v0));
                v1 = __uint_as_float(f2tf32(v1));
                v2 = __uint_as_float(f2tf32(v2));
                v3 = __uint_as_float(f2tf32(v3));
            }
            *(float2*)d0 = make_float2(v0, v1);
            *(float2*)d1 = make_float2(v2, v3);
        }
    }
}

// ---------------------------------------------------------------------------
// RMSNorm + RoPE, warp-per-row (8 rows per 256-thr block), no block barriers.
// ---------------------------------------------------------------------------
__global__ __launch_bounds__(256) void norm_rope_kernel(const float* __restrict__ qscale,
                                                        const float* __restrict__ kscale) {
    int wid = threadIdx.x >> 5, lane = threadIdx.x & 31;
    int row = blockIdx.x * 8 + wid;
    const int QROWS = B_ * NH_ * T_;
    float* data;
    const float* scale;
    int b, t;
    if (row < QROWS) {
        data = g_q + (size_t)row * H_;
        scale = qscale;
        b = row / (NH_ * T_);
        t = row % T_;
    } else {
        int r = row - QROWS;
        data = g_k + (size_t)r * H_;
        scale = kscale;
        b = r / (KH_ * T_);
        t = r % T_;
    }

    float4 v = *(const float4*)(data + lane * 4);
    float ss = v.x * v.x + v.y * v.y + v.z * v.z + v.w * v.w;
#pragma unroll
    for (int o = 16; o; o >>= 1) ss += __shfl_xor_sync(0xffffffffu, ss, o);
    float rinv = rsqrtf(ss * (1.0f / 128.0f) + 1e-6f);

    float4 sc = *(const float4*)(scale + lane * 4);
    float x[4] = { sc.x * v.x * rinv, sc.y * v.y * rinv,
                   sc.z * v.z * rinv, sc.w * v.w * rinv };

    int pos = g_pos[b * T_ + t];
    int j = lane & 15;
    bool lowHalf = (lane < 16);
    float out[4];
#pragma unroll
    for (int k = 0; k < 4; k++) {
        int idx = j * 4 + k;
        float inv = exp2f(-((float)idx * (1.0f / 64.0f)) * 19.931568569324174f);
        float ang = (float)pos * inv;
        float sn, cs;
        sincosf(ang, &sn, &cs);
        float xo = __shfl_xor_sync(0xffffffffu, x[k], 16);
        float r = lowHalf ? (x[k] * cs - xo * sn) : (x[k] * cs + xo * sn);
        out[k] = __uint_as_float(f2tf32(r));
    }
    *(float4*)(data + lane * 4) = make_float4(out[0], out[1], out[2], out[3]);
}

// ---------------------------------------------------------------------------
// Flash attention: FA2-style warp ownership (8 warps x 16 rows), Q fragments
// HOISTED INTO REGISTERS (loaded once from smem in the prologue), register
// softmax, 2 barriers/tile. Q tile 128, KV 64, LPT. smem 174,080B.
// ---------------------------------------------------------------------------
#define SQ_OFF   0
#define SK_OFF   (SQ_OFF + 128 * 132)
#define SV_OFF   (SK_OFF + 64 * 132)
#define SS_OFF   (SV_OFF + 64 * 136)
#define PT_OFF   (SS_OFF + 128 * 68)
#define ST_OFF   (PT_OFF + 128)
#define PS_OFF   (ST_OFF + 128)
#define SSG_OFF  (PS_OFF + 64)
#define ATTN_SMEM_WORDS (SSG_OFF + 64)

__global__ __launch_bounds__(256, 1) void attn_kernel(const int* __restrict__ seg) {
    extern __shared__ uint32_t smu[];
    uint32_t* sQ  = smu + SQ_OFF;
    uint32_t* sK  = smu + SK_OFF;
    uint32_t* sV  = smu + SV_OFF;
    uint32_t* sSu = smu + SS_OFF;
    int*      sPT = (int*)(smu + PT_OFF);
    int*      sST = (int*)(smu + ST_OFF);
    int*      sPS = (int*)(smu + PS_OFF);
    int*      sSG = (int*)(smu + SSG_OFF);

    uint32_t smem_base = (uint32_t)__cvta_generic_to_shared(smu);

    int tid = threadIdx.x;
    int warp = tid >> 5, lane = tid & 31;
    int g = lane >> 2, qd = lane & 3;

    int bid = blockIdx.x;
    int itile = 15 - (bid & 15);
    int n  = (bid >> 4) & 15;
    int b  = bid >> 8;
    int kvh = n >> 1;
    int t0 = itile * 128;

    const float* Qb = g_q + (size_t)(b * NH_ + n)   * T_ * H_;
    const float* Kb = g_k + (size_t)(b * KH_ + kvh) * T_ * H_;
    const float* Vb = g_v + (size_t)(b * KH_ + kvh) * T_ * H_;
    const int* posb = g_pos + b * T_;
    const int* segb = seg + b * T_;

    int lr = tid >> 5;
    int lc = (tid & 31) << 2;

    // Prologue: stage Q (group 0)
#pragma unroll
    for (int i = 0; i < 16; i++) {
        int r = lr + i * 8;
        cpa16(smem_base + (SQ_OFF + r * 132 + lc) * 4,
              Qb + (size_t)(t0 + r) * H_ + lc);
    }
    cpa_commit();

    if (tid < 128) {
        sPT[tid] = posb[t0 + tid];
        sST[tid] = segb[t0 + tid];
    }

    int r0 = warp * 16 + g, r1 = r0 + 8;

    // Wait for Q, then hoist this warp's Q fragments into registers.
    cpa_wait0();
    __syncthreads();
    uint32_t aq[16][4];
#pragma unroll
    for (int i = 0; i < 16; i++) {
        int k0 = i * 8;
        aq[i][0] = sQ[r0 * 132 + k0 + qd];
        aq[i][1] = sQ[r1 * 132 + k0 + qd];
        aq[i][2] = sQ[r0 * 132 + k0 + 4 + qd];
        aq[i][3] = sQ[r1 * 132 + k0 + 4 + qd];
    }

    float m0 = -3.0e38f, m1 = -3.0e38f, l0 = 0.0f, l1 = 0.0f;

    float cO[16][4];
#pragma unroll
    for (int i = 0; i < 16; i++)
#pragma unroll
        for (int j = 0; j < 4; j++) cO[i][j] = 0.0f;

    int numjt = 2 * itile + 2;
    for (int jt = 0; jt < numjt; jt++) {
        int s0 = jt * 64;

#pragma unroll
        for (int i = 0; i < 8; i++) {
            int r = lr + i * 8;
            cpa16(smem_base + (SK_OFF + r * 132 + lc) * 4,
                  Kb + (size_t)(s0 + r) * H_ + lc);
            cpa16(smem_base + (SV_OFF + r * 136 + lc) * 4,
                  Vb + (size_t)(s0 + r) * H_ + lc);
        }
        cpa_commit();
        if (tid < 64) {
            sPS[tid] = posb[s0 + tid];
            sSG[tid] = segb[s0 + tid];
        }
        cpa_wait0();
        __syncthreads();     // (1) K/V + pos/seg ready

        // ---- S = Q K^T ; A operands from registers ----
        float cS[8][4];
#pragma unroll
        for (int nt = 0; nt < 8; nt++)
#pragma unroll
            for (int j = 0; j < 4; j++) cS[nt][j] = 0.0f;

#pragma unroll
        for (int i = 0; i < 16; i++) {
            int k0 = i * 8;
#pragma unroll
            for (int nt = 0; nt < 8; nt++) {
                int bc = nt * 8 + g;
                uint32_t b0 = sK[bc * 132 + k0 + qd];
                uint32_t b1 = sK[bc * 132 + k0 + 4 + qd];
                mma_tf32(cS[nt], aq[i][0], aq[i][1], aq[i][2], aq[i][3], b0, b1);
            }
        }

        int pt0 = sPT[r0], st0 = sST[r0];
        int pt1 = sPT[r1], st1 = sST[r1];
        float v0[8][2], v1[8][2];
#pragma unroll
        for (int nt = 0; nt < 8; nt++) {
            int col = nt * 8 + qd * 2;
            int ps0 = sPS[col], ss0 = sSG[col];
            int ps1 = sPS[col + 1], ss1 = sSG[col + 1];
            v0[nt][0] = (ps0 <= pt0 && ss0 == st0) ? cS[nt][0] * SCALE_ : KMASK_;
            v0[nt][1] = (ps1 <= pt0 && ss1 == st0) ? cS[nt][1] * SCALE_ : KMASK_;
            v1[nt][0] = (ps0 <= pt1 && ss0 == st1) ? cS[nt][2] * SCALE_ : KMASK_;
            v1[nt][1] = (ps1 <= pt1 && ss1 == st1) ? cS[nt][3] * SCALE_ : KMASK_;
        }

        float mx0 = KMASK_, mx1 = KMASK_;
#pragma unroll
        for (int nt = 0; nt < 8; nt++) {
            mx0 = fmaxf(mx0, fmaxf(v0[nt][0], v0[nt][1]));
            mx1 = fmaxf(mx1, fmaxf(v1[nt][0], v1[nt][1]));
        }
        mx0 = fmaxf(mx0, __shfl_xor_sync(0xffffffffu, mx0, 1));
        mx0 = fmaxf(mx0, __shfl_xor_sync(0xffffffffu, mx0, 2));
        mx1 = fmaxf(mx1, __shfl_xor_sync(0xffffffffu, mx1, 1));
        mx1 = fmaxf(mx1, __shfl_xor_sync(0xffffffffu, mx1, 2));
        float mn0 = fmaxf(m0, mx0), mn1 = fmaxf(m1, mx1);

        float sum0 = 0.0f, sum1 = 0.0f;
#pragma unroll
        for (int nt = 0; nt < 8; nt++) {
            int col = nt * 8 + qd * 2;
            float p00 = __expf(v0[nt][0] - mn0);
            float p01 = __expf(v0[nt][1] - mn0);
            float p10 = __expf(v1[nt][0] - mn1);
            float p11 = __expf(v1[nt][1] - mn1);
            sum0 += p00 + p01;
            sum1 += p10 + p11;
            sSu[r0 * 68 + col]     = f2tf32(p00);
            sSu[r0 * 68 + col + 1] = f2tf32(p01);
            sSu[r1 * 68 + col]     = f2tf32(p10);
            sSu[r1 * 68 + col + 1] = f2tf32(p11);
        }
        sum0 += __shfl_xor_sync(0xffffffffu, sum0, 1);
        sum0 += __shfl_xor_sync(0xffffffffu, sum0, 2);
        sum1 += __shfl_xor_sync(0xffffffffu, sum1, 1);
        sum1 += __shfl_xor_sync(0xffffffffu, sum1, 2);

        float f0 = __expf(m0 - mn0), f1 = __expf(m1 - mn1);
        l0 = l0 * f0 + sum0;
        l1 = l1 * f1 + sum1;
        m0 = mn0; m1 = mn1;

#pragma unroll
        for (int nt = 0; nt < 16; nt++) {
            cO[nt][0] *= f0; cO[nt][1] *= f0;
            cO[nt][2] *= f1; cO[nt][3] *= f1;
        }
        __syncwarp();

#pragma unroll
        for (int k0 = 0; k0 < 64; k0 += 8) {
            uint32_t a0 = sSu[r0 * 68 + k0 + qd];
            uint32_t a1 = sSu[r1 * 68 + k0 + qd];
            uint32_t a2 = sSu[r0 * 68 + k0 + 4 + qd];
            uint32_t a3 = sSu[r1 * 68 + k0 + 4 + qd];
#pragma unroll
            for (int nt = 0; nt < 16; nt++) {
                int vc = nt * 8 + g;
                uint32_t b0 = sV[(k0 + qd) * 136 + vc];
                uint32_t b1 = sV[(k0 + 4 + qd) * 136 + vc];
                mma_tf32(cO[nt], a0, a1, a2, a3, b0, b1);
            }
        }
        __syncthreads();     // (2) all warps done with sK/sV/sPS
    }

    float inv0 = 1.0f / l0;
    float inv1 = 1.0f / l1;
#pragma unroll
    for (int nt = 0; nt < 16; nt++) {
        int col = nt * 8 + qd * 2;
        float* d0 = g_o + ((size_t)(b * T_ + t0 + r0) * NH_ + n) * H_ + col;
        float* d1 = g_o + ((size_t)(b * T_ + t0 + r1) * NH_ + n) * H_ + col;
        *(float2*)d0 = make_float2(__uint_as_float(f2tf32(cO[nt][0] * inv0)),
                                   __uint_as_float(f2tf32(cO[nt][1] * inv0)));
        *(float2*)d1 = make_float2(__uint_as_float(f2tf32(cO[nt][2] * inv1)),
                                   __uint_as_float(f2tf32(cO[nt][3] * inv1)));
    }
}

// ---------------------------------------------------------------------------
// Output projection (tf32 mma, cp.async 2-stage, 256 threads — R13 proven).
// ---------------------------------------------------------------------------
__global__ __launch_bounds__(256) void sgemm_out(float* __restrict__ out) {
    extern __shared__ uint32_t smg[];
    uint32_t* sA = smg;
    uint32_t* sB = smg + GEMM_SA_WORDS;

    int tid = threadIdx.x;
    int warp = tid >> 5, lane = tid & 31;
    int g = lane >> 2, qd = lane & 3;
    int wm = warp & 1, wn = warp >> 1;

    int cn = blockIdx.x * 128;
    int rm = blockIdx.y * 128;

    uint32_t sA_base = (uint32_t)__cvta_generic_to_shared(sA);
    uint32_t sB_base = (uint32_t)__cvta_generic_to_shared(sB);

    int arA = tid >> 3, acA = (tid & 7) << 2;
    int arB = tid >> 5, acB = (tid & 31) << 2;

    float c[4][4][4];
#pragma unroll
    for (int mt = 0; mt < 4; mt++)
#pragma unroll
        for (int nt = 0; nt < 4; nt++)
#pragma unroll
            for (int i = 0; i < 4; i++) c[mt][nt][i] = 0.0f;

    auto load_stage = [&](int kk, int st) {
#pragma unroll
        for (int i = 0; i < 4; i++) {
            int r = arA + i * 32;
            cpa16(sA_base + (st * 128 * 36 + r * 36 + acA) * 4,
                  g_o + (size_t)(rm + r) * (NH_ * H_) + kk + acA);
        }
#pragma unroll
        for (int i = 0; i < 4; i++) {
            int r = arB + i * 8;
            cpa16(sB_base + (st * 32 * 136 + r * 136 + acB) * 4,
                  g_wo + (size_t)(kk + r) * D_ + cn + acB);
        }
        cpa_commit();
    };

    load_stage(0, 0);

    const int KT = (NH_ * H_) / 32;
    for (int kt = 0; kt < KT; kt++) {
        if (kt + 1 < KT) load_stage((kt + 1) * 32, (kt + 1) & 1);
        if (kt + 1 < KT) cpa_wait1(); else cpa_wait0();
        __syncthreads();

        const uint32_t* A  = sA + (kt & 1) * 128 * 36;
        const uint32_t* Bm = sB + (kt & 1) * 32 * 136;
#pragma unroll
        for (int ks = 0; ks < 4; ks++) {
            int k0 = ks * 8;
            uint32_t a[4][4];
#pragma unroll
            for (int mt = 0; mt < 4; mt++) {
                int ar = wm * 64 + mt * 16 + g;
                a[mt][0] = A[ar * 36 + k0 + qd];
                a[mt][1] = A[(ar + 8) * 36 + k0 + qd];
                a[mt][2] = A[ar * 36 + k0 + 4 + qd];
                a[mt][3] = A[(ar + 8) * 36 + k0 + 4 + qd];
            }
            uint32_t b[4][2];
#pragma unroll
            for (int nt = 0; nt < 4; nt++) {
                int bc = wn * 32 + nt * 8 + g;
                b[nt][0] = Bm[(k0 + qd) * 136 + bc];
                b[nt][1] = Bm[(k0 + 4 + qd) * 136 + bc];
            }
#pragma unroll
            for (int mt = 0; mt < 4; mt++)
#pragma unroll
                for (int nt = 0; nt < 4; nt++)
                    mma_tf32(c[mt][nt], a[mt][0], a[mt][1], a[mt][2], a[mt][3],
                             b[nt][0], b[nt][1]);
        }
        __syncthreads();
    }

#pragma unroll
    for (int mt = 0; mt < 4; mt++) {
#pragma unroll
        for (int nt = 0; nt < 4; nt++) {
            int col = cn + wn * 32 + nt * 8 + qd * 2;
            int rr0 = rm + wm * 64 + mt * 16 + g;
            int rr1 = rr0 + 8;
            *(float2*)(out + (size_t)rr0 * D_ + col) = make_float2(c[mt][nt][0], c[mt][nt][1]);
            *(float2*)(out + (size_t)rr1 * D_ + col) = make_float2(c[mt][nt][2], c[mt][nt][3]);
        }
    }
}

// ---------------------------------------------------------------------------
extern "C" void kernel_launch(void* const* d_in, const int* in_sizes, int n_in,
                              void* d_out, int out_size) {
    const float* x  = (const float*)d_in[0];
    const int*   sg = (const int*)d_in[1];
    const float* wq = (const float*)d_in[2];
    const float* wk = (const float*)d_in[3];
    const float* wv = (const float*)d_in[4];
    const float* wo = (const float*)d_in[5];
    const float* qs = (const float*)d_in[6];
    const float* ks = (const float*)d_in[7];
    float* out = (float*)d_out;

    cudaFuncSetAttribute(sgemm_qkv, cudaFuncAttributeMaxDynamicSharedMemorySize,
                         GEMM_SMEM_BYTES);
    cudaFuncSetAttribute(sgemm_out, cudaFuncAttributeMaxDynamicSharedMemorySize,
                         GEMM_SMEM_BYTES);
    cudaFuncSetAttribute(attn_kernel, cudaFuncAttributeMaxDynamicSharedMemorySize,
                         ATTN_SMEM_WORDS * 4);

    pos_kernel<<<B_, 256>>>(sg);                                        // 1
    round_x_kernel<<<512, 256>>>(x);                                    // 2
    round_w_kernel<<<512, 256>>>(wq, wk, wv, wo);                       // 3
    sgemm_qkv<<<dim3(32, 32), 128, GEMM_SMEM_BYTES>>>();                // 4
    norm_rope_kernel<<<(B_ * (NH_ + KH_) * T_) / 8, 256>>>(qs, ks);     // 5
    attn_kernel<<<B_ * NH_ * 16, 256, ATTN_SMEM_WORDS * 4>>>(sg);       // 6
    sgemm_out<<<dim3(8, 32), 256, GEMM_SMEM_BYTES>>>(out);              // 7
}

// round 17
// speedup vs baseline: 1.0814x; 1.0359x over previous
#include <cuda_runtime.h>
#include <cuda_bf16.h>
#include <cstdint>

#define B_ 2
#define T_ 2048
#define D_ 1024
#define NH_ 16
#define KH_ 8
#define H_ 128

static constexpr float SCALE_ = 0.08838834764831845f;   // 128^-0.5
static constexpr float KMASK_ = -3.4028234663852886e38f;

// Scratch (device globals; no runtime allocation allowed)
__device__ float g_q[(size_t)B_ * NH_ * T_ * H_];   // [B][N][T][H] (tf32-rounded)
__device__ float g_k[(size_t)B_ * KH_ * T_ * H_];   // [B][K][S][H] (tf32-rounded)
__device__ float g_v[(size_t)B_ * KH_ * T_ * H_];   // [B][K][S][H] (tf32-rounded)
__device__ float g_o[(size_t)B_ * T_ * NH_ * H_];   // [B][T][N][H] (tf32-rounded)
__device__ int   g_pos[B_ * T_];
// tf32-rounded copies of inputs
__device__ float g_x [(size_t)B_ * T_ * D_];
__device__ float g_wq[(size_t)D_ * NH_ * H_];
__device__ float g_wk[(size_t)D_ * KH_ * H_];
__device__ float g_wv[(size_t)D_ * KH_ * H_];
__device__ float g_wo[(size_t)NH_ * H_ * D_];

// ---------------------------------------------------------------------------
__device__ __forceinline__ uint32_t f2tf32(float x) {
    uint32_t r;
    asm("cvt.rna.tf32.f32 %0, %1;" : "=r"(r) : "f"(x));
    return r;
}

__device__ __forceinline__ void mma_tf32(float* c,
                                         uint32_t a0, uint32_t a1, uint32_t a2, uint32_t a3,
                                         uint32_t b0, uint32_t b1) {
    asm volatile(
        "mma.sync.aligned.m16n8k8.row.col.f32.tf32.tf32.f32 "
        "{%0,%1,%2,%3}, {%4,%5,%6,%7}, {%8,%9}, {%0,%1,%2,%3};\n"
        : "+f"(c[0]), "+f"(c[1]), "+f"(c[2]), "+f"(c[3])
        : "r"(a0), "r"(a1), "r"(a2), "r"(a3), "r"(b0), "r"(b1));
}

__device__ __forceinline__ void cpa16(uint32_t saddr, const void* gptr) {
    asm volatile("cp.async.ca.shared.global [%0], [%1], 16;\n"
                 :: "r"(saddr), "l"(gptr));
}
__device__ __forceinline__ void cpa_commit() {
    asm volatile("cp.async.commit_group;\n" ::: "memory");
}
__device__ __forceinline__ void cpa_wait0() {
    asm volatile("cp.async.wait_group 0;\n" ::: "memory");
}
__device__ __forceinline__ void cpa_wait1() {
    asm volatile("cp.async.wait_group 1;\n" ::: "memory");
}

// ---------------------------------------------------------------------------
// Positions from segment ids.
// ---------------------------------------------------------------------------
__global__ __launch_bounds__(256) void pos_kernel(const int* __restrict__ seg) {
    int b = blockIdx.x;
    int tid = threadIdx.x;
    __shared__ int sred[256];

    int mv = -2147483647 - 1;
    for (int t = tid; t < T_; t += 256) mv = max(mv, seg[b * T_ + t]);
    sred[tid] = mv;
    __syncthreads();
    for (int st = 128; st > 0; st >>= 1) {
        if (tid < st) sred[tid] = max(sred[tid], sred[tid + st]);
        __syncthreads();
    }
    int maxv = sred[0];
    __syncthreads();

    int mi = 0x7fffffff;
    for (int t = tid; t < T_; t += 256)
        if (seg[b * T_ + t] == maxv) mi = min(mi, t);
    sred[tid] = mi;
    __syncthreads();
    for (int st = 128; st > 0; st >>= 1) {
        if (tid < st) sred[tid] = min(sred[tid], sred[tid + st]);
        __syncthreads();
    }
    int off = sred[0];

    for (int t = tid; t < T_; t += 256) {
        int s = seg[b * T_ + t];
        g_pos[b * T_ + t] = (s != 0) ? (t - off) : (1 << 30);
    }
}

// ---------------------------------------------------------------------------
// Round x to tf32 into g_x.
// ---------------------------------------------------------------------------
__global__ __launch_bounds__(256) void round_x_kernel(const float* __restrict__ src) {
    const int n4 = (B_ * T_ * D_) / 4;
    int i = blockIdx.x * 256 + threadIdx.x;
    int stride = gridDim.x * 256;
    for (; i < n4; i += stride) {
        float4 v = *(const float4*)(src + (size_t)i * 4);
        v.x = __uint_as_float(f2tf32(v.x));
        v.y = __uint_as_float(f2tf32(v.y));
        v.z = __uint_as_float(f2tf32(v.z));
        v.w = __uint_as_float(f2tf32(v.w));
        *(float4*)(g_x + (size_t)i * 4) = v;
    }
}

// ---------------------------------------------------------------------------
// Round all 4 weight tensors to tf32 (flat index over concat).
// ---------------------------------------------------------------------------
__global__ __launch_bounds__(256) void round_w_kernel(const float* __restrict__ wq,
                                                      const float* __restrict__ wk,
                                                      const float* __restrict__ wv,
                                                      const float* __restrict__ wo) {
    const int N4 = 1572864;
    int i = blockIdx.x * 256 + threadIdx.x;
    int stride = gridDim.x * 256;
    for (; i < N4; i += stride) {
        const float* src;
        float* dst;
        int j;
        if (i < 524288)       { src = wq; dst = g_wq; j = i; }
        else if (i < 786432)  { src = wk; dst = g_wk; j = i - 524288; }
        else if (i < 1048576) { src = wv; dst = g_wv; j = i - 786432; }
        else                  { src = wo; dst = g_wo; j = i - 1048576; }
        float4 v = *(const float4*)(src + (size_t)j * 4);
        v.x = __uint_as_float(f2tf32(v.x));
        v.y = __uint_as_float(f2tf32(v.y));
        v.z = __uint_as_float(f2tf32(v.z));
        v.w = __uint_as_float(f2tf32(v.w));
        *(float4*)(dst + (size_t)j * 4) = v;
    }
}

// ---------------------------------------------------------------------------
// QKV projection GEMM: 128 threads / 4 warps, warp tile 64x64.
// ---------------------------------------------------------------------------
#define GEMM_SA_WORDS (2 * 128 * 36)
#define GEMM_SB_WORDS (2 * 32 * 136)
#define GEMM_SMEM_BYTES ((GEMM_SA_WORDS + GEMM_SB_WORDS) * 4)

__global__ __launch_bounds__(128) void sgemm_qkv() {
    extern __shared__ uint32_t smg[];
    uint32_t* sA = smg;
    uint32_t* sB = smg + GEMM_SA_WORDS;

    int tid = threadIdx.x;
    int warp = tid >> 5, lane = tid & 31;
    int g = lane >> 2, qd = lane & 3;
    int wm = warp & 1, wn = warp >> 1;

    int cn = blockIdx.x * 128;
    int rm = blockIdx.y * 128;

    const float* W;
    int ldb, mode, colOff;
    if (cn < 2048)      { W = g_wq; ldb = NH_ * H_; colOff = cn;        mode = 0; }
    else if (cn < 3072) { W = g_wk; ldb = KH_ * H_; colOff = cn - 2048; mode = 1; }
    else                { W = g_wv; ldb = KH_ * H_; colOff = cn - 3072; mode = 2; }
    int head = colOff >> 7;

    uint32_t sA_base = (uint32_t)__cvta_generic_to_shared(sA);
    uint32_t sB_base = (uint32_t)__cvta_generic_to_shared(sB);

    int arA = tid >> 3, acA = (tid & 7) << 2;
    int arB = tid >> 5, acB = (tid & 31) << 2;

    float c[4][8][4];
#pragma unroll
    for (int mt = 0; mt < 4; mt++)
#pragma unroll
        for (int nt = 0; nt < 8; nt++)
#pragma unroll
            for (int i = 0; i < 4; i++) c[mt][nt][i] = 0.0f;

    auto load_stage = [&](int kk, int st) {
#pragma unroll
        for (int i = 0; i < 8; i++) {
            int r = arA + i * 16;
            cpa16(sA_base + (st * 128 * 36 + r * 36 + acA) * 4,
                  g_x + (size_t)(rm + r) * D_ + kk + acA);
        }
#pragma unroll
        for (int i = 0; i < 8; i++) {
            int r = arB + i * 4;
            cpa16(sB_base + (st * 32 * 136 + r * 136 + acB) * 4,
                  W + (size_t)(kk + r) * ldb + colOff + acB);
        }
        cpa_commit();
    };

    load_stage(0, 0);

    const int KT = D_ / 32;
    for (int kt = 0; kt < KT; kt++) {
        if (kt + 1 < KT) load_stage((kt + 1) * 32, (kt + 1) & 1);
        if (kt + 1 < KT) cpa_wait1(); else cpa_wait0();
        __syncthreads();

        const uint32_t* A  = sA + (kt & 1) * 128 * 36;
        const uint32_t* Bm = sB + (kt & 1) * 32 * 136;
#pragma unroll
        for (int ks = 0; ks < 4; ks++) {
            int k0 = ks * 8;
            uint32_t a[4][4];
#pragma unroll
            for (int mt = 0; mt < 4; mt++) {
                int ar = wm * 64 + mt * 16 + g;
                a[mt][0] = A[ar * 36 + k0 + qd];
                a[mt][1] = A[(ar + 8) * 36 + k0 + qd];
                a[mt][2] = A[ar * 36 + k0 + 4 + qd];
                a[mt][3] = A[(ar + 8) * 36 + k0 + 4 + qd];
            }
            uint32_t b[8][2];
#pragma unroll
            for (int nt = 0; nt < 8; nt++) {
                int bc = wn * 64 + nt * 8 + g;
                b[nt][0] = Bm[(k0 + qd) * 136 + bc];
                b[nt][1] = Bm[(k0 + 4 + qd) * 136 + bc];
            }
#pragma unroll
            for (int mt = 0; mt < 4; mt++)
#pragma unroll
                for (int nt = 0; nt < 8; nt++)
                    mma_tf32(c[mt][nt], a[mt][0], a[mt][1], a[mt][2], a[mt][3],
                             b[nt][0], b[nt][1]);
        }
        __syncthreads();
    }

    float* base = (mode == 0) ? g_q : (mode == 1 ? g_k : g_v);
    int heads = (mode == 0) ? NH_ : KH_;
    bool roundV = (mode == 2);
#pragma unroll
    for (int mt = 0; mt < 4; mt++) {
#pragma unroll
        for (int nt = 0; nt < 8; nt++) {
            int col = wn * 64 + nt * 8 + qd * 2;
            int rr0 = rm + wm * 64 + mt * 16 + g;
            int rr1 = rr0 + 8;
            int b0 = rr0 >> 11, t0 = rr0 & 2047;
            int b1 = rr1 >> 11, t1 = rr1 & 2047;
            float* d0 = base + ((size_t)(b0 * heads + head) * T_ + t0) * H_ + col;
            float* d1 = base + ((size_t)(b1 * heads + head) * T_ + t1) * H_ + col;
            float v0 = c[mt][nt][0], v1 = c[mt][nt][1];
            float v2 = c[mt][nt][2], v3 = c[mt][nt][3];
            if (roundV) {
                v0 = __uint_as_float(f2tf32(v0));
                v1 = __uint_as_float(f2tf32(v1));
                v2 = __uint_as_float(f2tf32(v2));
                v3 = __uint_as_float(f2tf32(v3));
            }
            *(float2*)d0 = make_float2(v0, v1);
            *(float2*)d1 = make_float2(v2, v3);
        }
    }
}

// ---------------------------------------------------------------------------
// RMSNorm + RoPE, warp-per-row.
// ---------------------------------------------------------------------------
__global__ __launch_bounds__(256) void norm_rope_kernel(const float* __restrict__ qscale,
                                                        const float* __restrict__ kscale) {
    int wid = threadIdx.x >> 5, lane = threadIdx.x & 31;
    int row = blockIdx.x * 8 + wid;
    const int QROWS = B_ * NH_ * T_;
    float* data;
    const float* scale;
    int b, t;
    if (row < QROWS) {
        data = g_q + (size_t)row * H_;
        scale = qscale;
        b = row / (NH_ * T_);
        t = row % T_;
    } else {
        int r = row - QROWS;
        data = g_k + (size_t)r * H_;
        scale = kscale;
        b = r / (KH_ * T_);
        t = r % T_;
    }

    float4 v = *(const float4*)(data + lane * 4);
    float ss = v.x * v.x + v.y * v.y + v.z * v.z + v.w * v.w;
#pragma unroll
    for (int o = 16; o; o >>= 1) ss += __shfl_xor_sync(0xffffffffu, ss, o);
    float rinv = rsqrtf(ss * (1.0f / 128.0f) + 1e-6f);

    float4 sc = *(const float4*)(scale + lane * 4);
    float x[4] = { sc.x * v.x * rinv, sc.y * v.y * rinv,
                   sc.z * v.z * rinv, sc.w * v.w * rinv };

    int pos = g_pos[b * T_ + t];
    int j = lane & 15;
    bool lowHalf = (lane < 16);
    float out[4];
#pragma unroll
    for (int k = 0; k < 4; k++) {
        int idx = j * 4 + k;
        float inv = exp2f(-((float)idx * (1.0f / 64.0f)) * 19.931568569324174f);
        float ang = (float)pos * inv;
        float sn, cs;
        sincosf(ang, &sn, &cs);
        float xo = __shfl_xor_sync(0xffffffffu, x[k], 16);
        float r = lowHalf ? (x[k] * cs - xo * sn) : (x[k] * cs + xo * sn);
        out[k] = __uint_as_float(f2tf32(r));
    }
    *(float4*)(data + lane * 4) = make_float4(out[0], out[1], out[2], out[3]);
}

// ---------------------------------------------------------------------------
// Flash attention: FA2 warp ownership + Q in registers + DOUBLE-BUFFERED K/V
// with the odd-parity buffers aliased into the dead Q staging region.
// ONE block barrier per tile; K/V(jt+1) prefetch overlaps the whole tile.
// smem = 174,592 B.
// ---------------------------------------------------------------------------
#define REG_OFF   0
#define REG_WORDS 17152                     // >= max(Q 128*132, K1 8448 + V1 8704)
#define SK0_OFF   (REG_OFF + REG_WORDS)     // 64*132
#define SV0_OFF   (SK0_OFF + 64 * 132)      // 64*136
#define SS_OFF    (SV0_OFF + 64 * 136)      // 128*68 (P)
#define PT_OFF    (SS_OFF + 128 * 68)
#define ST_OFF    (PT_OFF + 128)
#define PS_OFF    (ST_OFF + 128)            // [2][64]
#define SSG_OFF   (PS_OFF + 128)            // [2][64]
#define ATTN_SMEM_WORDS (SSG_OFF + 128)

__global__ __launch_bounds__(256, 1) void attn_kernel(const int* __restrict__ seg) {
    extern __shared__ uint32_t smu[];
    uint32_t* sQ  = smu + REG_OFF;                 // prologue only (stride 132)
    uint32_t* sSu = smu + SS_OFF;
    int*      sPT = (int*)(smu + PT_OFF);
    int*      sST = (int*)(smu + ST_OFF);
    int*      sPS = (int*)(smu + PS_OFF);          // [2][64]
    int*      sSG = (int*)(smu + SSG_OFF);         // [2][64]

    uint32_t smem_base = (uint32_t)__cvta_generic_to_shared(smu);

    int tid = threadIdx.x;
    int warp = tid >> 5, lane = tid & 31;
    int g = lane >> 2, qd = lane & 3;

    int bid = blockIdx.x;
    int itile = 15 - (bid & 15);
    int n  = (bid >> 4) & 15;
    int b  = bid >> 8;
    int kvh = n >> 1;
    int t0 = itile * 128;

    const float* Qb = g_q + (size_t)(b * NH_ + n)   * T_ * H_;
    const float* Kb = g_k + (size_t)(b * KH_ + kvh) * T_ * H_;
    const float* Vb = g_v + (size_t)(b * KH_ + kvh) * T_ * H_;
    const int* posb = g_pos + b * T_;
    const int* segb = seg + b * T_;

    int lr = tid >> 5;
    int lc = (tid & 31) << 2;

    // K/V buffer word-offsets per parity: 0 -> SK0/SV0, 1 -> region alias
    auto koff = [&](int par) { return par ? (REG_OFF) : (SK0_OFF); };
    auto voff = [&](int par) { return par ? (REG_OFF + 64 * 132) : (SV0_OFF); };

    auto load_kv = [&](int s0, int par) {
        int kw = koff(par), vw = voff(par);
#pragma unroll
        for (int i = 0; i < 8; i++) {
            int r = lr + i * 8;
            cpa16(smem_base + (kw + r * 132 + lc) * 4,
                  Kb + (size_t)(s0 + r) * H_ + lc);
            cpa16(smem_base + (vw + r * 136 + lc) * 4,
                  Vb + (size_t)(s0 + r) * H_ + lc);
        }
        cpa_commit();
    };

    // Prologue: Q into region + K0/V0 into parity-0 buffers (one group)
#pragma unroll
    for (int i = 0; i < 16; i++) {
        int r = lr + i * 8;
        cpa16(smem_base + (REG_OFF + r * 132 + lc) * 4,
              Qb + (size_t)(t0 + r) * H_ + lc);
    }
#pragma unroll
    for (int i = 0; i < 8; i++) {
        int r = lr + i * 8;
        cpa16(smem_base + (SK0_OFF + r * 132 + lc) * 4, Kb + (size_t)r * H_ + lc);
        cpa16(smem_base + (SV0_OFF + r * 136 + lc) * 4, Vb + (size_t)r * H_ + lc);
    }
    cpa_commit();

    if (tid < 128) {
        sPT[tid] = posb[t0 + tid];
        sST[tid] = segb[t0 + tid];
    }
    if (tid < 64) {               // pos/seg for tile 0 (parity 0)
        sPS[tid] = posb[tid];
        sSG[tid] = segb[tid];
    }

    int r0 = warp * 16 + g, r1 = r0 + 8;

    cpa_wait0();
    __syncthreads();
    // Hoist Q fragments to registers (region becomes reusable after the
    // first in-loop barrier, which every warp reaches only after this).
    uint32_t aq[16][4];
#pragma unroll
    for (int i = 0; i < 16; i++) {
        int k0 = i * 8;
        aq[i][0] = sQ[r0 * 132 + k0 + qd];
        aq[i][1] = sQ[r1 * 132 + k0 + qd];
        aq[i][2] = sQ[r0 * 132 + k0 + 4 + qd];
        aq[i][3] = sQ[r1 * 132 + k0 + 4 + qd];
    }

    float m0 = -3.0e38f, m1 = -3.0e38f, l0 = 0.0f, l1 = 0.0f;

    float cO[16][4];
#pragma unroll
    for (int i = 0; i < 16; i++)
#pragma unroll
        for (int j = 0; j < 4; j++) cO[i][j] = 0.0f;

    int numjt = 2 * itile + 2;
    for (int jt = 0; jt < numjt; jt++) {
        int par = jt & 1;

        cpa_wait0();             // K/V(jt) landed (prefetched a full tile ago)
        __syncthreads();         // ONE barrier: publishes data, retires reads

        bool more = (jt + 1 < numjt);
        if (more) {
            load_kv((jt + 1) * 64, par ^ 1);     // overlaps entire tile jt
            if (tid < 64) {
                sPS[(par ^ 1) * 64 + tid] = posb[(jt + 1) * 64 + tid];
                sSG[(par ^ 1) * 64 + tid] = segb[(jt + 1) * 64 + tid];
            }
        }

        const uint32_t* Kt = smu + koff(par);
        const uint32_t* Vt = smu + voff(par);
        const int* ps = sPS + par * 64;
        const int* sg2 = sSG + par * 64;

        // ---- S = Q K^T (A from registers) ----
        float cS[8][4];
#pragma unroll
        for (int nt = 0; nt < 8; nt++)
#pragma unroll
            for (int j = 0; j < 4; j++) cS[nt][j] = 0.0f;

#pragma unroll
        for (int i = 0; i < 16; i++) {
            int k0 = i * 8;
#pragma unroll
            for (int nt = 0; nt < 8; nt++) {
                int bc = nt * 8 + g;
                uint32_t b0 = Kt[bc * 132 + k0 + qd];
                uint32_t b1 = Kt[bc * 132 + k0 + 4 + qd];
                mma_tf32(cS[nt], aq[i][0], aq[i][1], aq[i][2], aq[i][3], b0, b1);
            }
        }

        int pt0 = sPT[r0], st0 = sST[r0];
        int pt1 = sPT[r1], st1 = sST[r1];
        float v0[8][2], v1[8][2];
#pragma unroll
        for (int nt = 0; nt < 8; nt++) {
            int col = nt * 8 + qd * 2;
            int ps0 = ps[col], ss0 = sg2[col];
            int ps1 = ps[col + 1], ss1 = sg2[col + 1];
            v0[nt][0] = (ps0 <= pt0 && ss0 == st0) ? cS[nt][0] * SCALE_ : KMASK_;
            v0[nt][1] = (ps1 <= pt0 && ss1 == st0) ? cS[nt][1] * SCALE_ : KMASK_;
            v1[nt][0] = (ps0 <= pt1 && ss0 == st1) ? cS[nt][2] * SCALE_ : KMASK_;
            v1[nt][1] = (ps1 <= pt1 && ss1 == st1) ? cS[nt][3] * SCALE_ : KMASK_;
        }

        float mx0 = KMASK_, mx1 = KMASK_;
#pragma unroll
        for (int nt = 0; nt < 8; nt++) {
            mx0 = fmaxf(mx0, fmaxf(v0[nt][0], v0[nt][1]));
            mx1 = fmaxf(mx1, fmaxf(v1[nt][0], v1[nt][1]));
        }
        mx0 = fmaxf(mx0, __shfl_xor_sync(0xffffffffu, mx0, 1));
        mx0 = fmaxf(mx0, __shfl_xor_sync(0xffffffffu, mx0, 2));
        mx1 = fmaxf(mx1, __shfl_xor_sync(0xffffffffu, mx1, 1));
        mx1 = fmaxf(mx1, __shfl_xor_sync(0xffffffffu, mx1, 2));
        float mn0 = fmaxf(m0, mx0), mn1 = fmaxf(m1, mx1);

        float sum0 = 0.0f, sum1 = 0.0f;
#pragma unroll
        for (int nt = 0; nt < 8; nt++) {
            int col = nt * 8 + qd * 2;
            float p00 = __expf(v0[nt][0] - mn0);
            float p01 = __expf(v0[nt][1] - mn0);
            float p10 = __expf(v1[nt][0] - mn1);
            float p11 = __expf(v1[nt][1] - mn1);
            sum0 += p00 + p01;
            sum1 += p10 + p11;
            sSu[r0 * 68 + col]     = f2tf32(p00);
            sSu[r0 * 68 + col + 1] = f2tf32(p01);
            sSu[r1 * 68 + col]     = f2tf32(p10);
            sSu[r1 * 68 + col + 1] = f2tf32(p11);
        }
        sum0 += __shfl_xor_sync(0xffffffffu, sum0, 1);
        sum0 += __shfl_xor_sync(0xffffffffu, sum0, 2);
        sum1 += __shfl_xor_sync(0xffffffffu, sum1, 1);
        sum1 += __shfl_xor_sync(0xffffffffu, sum1, 2);

        float f0 = __expf(m0 - mn0), f1 = __expf(m1 - mn1);
        l0 = l0 * f0 + sum0;
        l1 = l1 * f1 + sum1;
        m0 = mn0; m1 = mn1;

#pragma unroll
        for (int nt = 0; nt < 16; nt++) {
            cO[nt][0] *= f0; cO[nt][1] *= f0;
            cO[nt][2] *= f1; cO[nt][3] *= f1;
        }
        __syncwarp();

#pragma unroll
        for (int k0 = 0; k0 < 64; k0 += 8) {
            uint32_t a0 = sSu[r0 * 68 + k0 + qd];
            uint32_t a1 = sSu[r1 * 68 + k0 + qd];
            uint32_t a2 = sSu[r0 * 68 + k0 + 4 + qd];
            uint32_t a3 = sSu[r1 * 68 + k0 + 4 + qd];
#pragma unroll
            for (int nt = 0; nt < 16; nt++) {
                int vc = nt * 8 + g;
                uint32_t b0 = Vt[(k0 + qd) * 136 + vc];
                uint32_t b1 = Vt[(k0 + 4 + qd) * 136 + vc];
                mma_tf32(cO[nt], a0, a1, a2, a3, b0, b1);
            }
        }
        // no trailing barrier: next iteration's single barrier protects
        // the parity buffers before they are overwritten.
    }

    float inv0 = 1.0f / l0;
    float inv1 = 1.0f / l1;
#pragma unroll
    for (int nt = 0; nt < 16; nt++) {
        int col = nt * 8 + qd * 2;
        float* d0 = g_o + ((size_t)(b * T_ + t0 + r0) * NH_ + n) * H_ + col;
        float* d1 = g_o + ((size_t)(b * T_ + t0 + r1) * NH_ + n) * H_ + col;
        *(float2*)d0 = make_float2(__uint_as_float(f2tf32(cO[nt][0] * inv0)),
                                   __uint_as_float(f2tf32(cO[nt][1] * inv0)));
        *(float2*)d1 = make_float2(__uint_as_float(f2tf32(cO[nt][2] * inv1)),
                                   __uint_as_float(f2tf32(cO[nt][3] * inv1)));
    }
}

// ---------------------------------------------------------------------------
// Output projection (tf32 mma, cp.async 2-stage, 256 threads).
// ---------------------------------------------------------------------------
__global__ __launch_bounds__(256) void sgemm_out(float* __restrict__ out) {
    extern __shared__ uint32_t smg[];
    uint32_t* sA = smg;
    uint32_t* sB = smg + GEMM_SA_WORDS;

    int tid = threadIdx.x;
    int warp = tid >> 5, lane = tid & 31;
    int g = lane >> 2, qd = lane & 3;
    int wm = warp & 1, wn = warp >> 1;

    int cn = blockIdx.x * 128;
    int rm = blockIdx.y * 128;

    uint32_t sA_base = (uint32_t)__cvta_generic_to_shared(sA);
    uint32_t sB_base = (uint32_t)__cvta_generic_to_shared(sB);

    int arA = tid >> 3, acA = (tid & 7) << 2;
    int arB = tid >> 5, acB = (tid & 31) << 2;

    float c[4][4][4];
#pragma unroll
    for (int mt = 0; mt < 4; mt++)
#pragma unroll
        for (int nt = 0; nt < 4; nt++)
#pragma unroll
            for (int i = 0; i < 4; i++) c[mt][nt][i] = 0.0f;

    auto load_stage = [&](int kk, int st) {
#pragma unroll
        for (int i = 0; i < 4; i++) {
            int r = arA + i * 32;
            cpa16(sA_base + (st * 128 * 36 + r * 36 + acA) * 4,
                  g_o + (size_t)(rm + r) * (NH_ * H_) + kk + acA);
        }
#pragma unroll
        for (int i = 0; i < 4; i++) {
            int r = arB + i * 8;
            cpa16(sB_base + (st * 32 * 136 + r * 136 + acB) * 4,
                  g_wo + (size_t)(kk + r) * D_ + cn + acB);
        }
        cpa_commit();
    };

    load_stage(0, 0);

    const int KT = (NH_ * H_) / 32;
    for (int kt = 0; kt < KT; kt++) {
        if (kt + 1 < KT) load_stage((kt + 1) * 32, (kt + 1) & 1);
        if (kt + 1 < KT) cpa_wait1(); else cpa_wait0();
        __syncthreads();

        const uint32_t* A  = sA + (kt & 1) * 128 * 36;
        const uint32_t* Bm = sB + (kt & 1) * 32 * 136;
#pragma unroll
        for (int ks = 0; ks < 4; ks++) {
            int k0 = ks * 8;
            uint32_t a[4][4];
#pragma unroll
            for (int mt = 0; mt < 4; mt++) {
                int ar = wm * 64 + mt * 16 + g;
                a[mt][0] = A[ar * 36 + k0 + qd];
                a[mt][1] = A[(ar + 8) * 36 + k0 + qd];
                a[mt][2] = A[ar * 36 + k0 + 4 + qd];
                a[mt][3] = A[(ar + 8) * 36 + k0 + 4 + qd];
            }
            uint32_t b[4][2];
#pragma unroll
            for (int nt = 0; nt < 4; nt++) {
                int bc = wn * 32 + nt * 8 + g;
                b[nt][0] = Bm[(k0 + qd) * 136 + bc];
                b[nt][1] = Bm[(k0 + 4 + qd) * 136 + bc];
            }
#pragma unroll
            for (int mt = 0; mt < 4; mt++)
#pragma unroll
                for (int nt = 0; nt < 4; nt++)
                    mma_tf32(c[mt][nt], a[mt][0], a[mt][1], a[mt][2], a[mt][3],
                             b[nt][0], b[nt][1]);
        }
        __syncthreads();
    }

#pragma unroll
    for (int mt = 0; mt < 4; mt++) {
#pragma unroll
        for (int nt = 0; nt < 4; nt++) {
            int col = cn + wn * 32 + nt * 8 + qd * 2;
            int rr0 = rm + wm * 64 + mt * 16 + g;
            int rr1 = rr0 + 8;
            *(float2*)(out + (size_t)rr0 * D_ + col) = make_float2(c[mt][nt][0], c[mt][nt][1]);
            *(float2*)(out + (size_t)rr1 * D_ + col) = make_float2(c[mt][nt][2], c[mt][nt][3]);
        }
    }
}

// ---------------------------------------------------------------------------
extern "C" void kernel_launch(void* const* d_in, const int* in_sizes, int n_in,
                              void* d_out, int out_size) {
    const float* x  = (const float*)d_in[0];
    const int*   sg = (const int*)d_in[1];
    const float* wq = (const float*)d_in[2];
    const float* wk = (const float*)d_in[3];
    const float* wv = (const float*)d_in[4];
    const float* wo = (const float*)d_in[5];
    const float* qs = (const float*)d_in[6];
    const float* ks = (const float*)d_in[7];
    float* out = (float*)d_out;

    cudaFuncSetAttribute(sgemm_qkv, cudaFuncAttributeMaxDynamicSharedMemorySize,
                         GEMM_SMEM_BYTES);
    cudaFuncSetAttribute(sgemm_out, cudaFuncAttributeMaxDynamicSharedMemorySize,
                         GEMM_SMEM_BYTES);
    cudaFuncSetAttribute(attn_kernel, cudaFuncAttributeMaxDynamicSharedMemorySize,
                         ATTN_SMEM_WORDS * 4);

    pos_kernel<<<B_, 256>>>(sg);                                        // 1
    round_x_kernel<<<512, 256>>>(x);                                    // 2
    round_w_kernel<<<512, 256>>>(wq, wk, wv, wo);                       // 3
    sgemm_qkv<<<dim3(32, 32), 128, GEMM_SMEM_BYTES>>>();                // 4
    norm_rope_kernel<<<(B_ * (NH_ + KH_) * T_) / 8, 256>>>(qs, ks);     // 5
    attn_kernel<<<B_ * NH_ * 16, 256, ATTN_SMEM_WORDS * 4>>>(sg);       // 6
    sgemm_out<<<dim3(8, 32), 256, GEMM_SMEM_BYTES>>>(out);              // 7
}